// round 10
// baseline (speedup 1.0000x reference)
#include <cuda_runtime.h>
#include <cuda_bf16.h>
#include <mma.h>
#include <cstdint>

using namespace nvcuda;

#define NODES_MAX 100000
#define EDGES_MAX 300000
#define HDIM 256
#define FIN 128

// ---------------- scratch (allocation-free rule: __device__ globals) ----------------
__device__ __align__(16) float g_h[(size_t)NODES_MAX * HDIM];
__device__ __align__(16) float g_m[(size_t)NODES_MAX * HDIM];
__device__ float g_dinv[NODES_MAX];
__device__ int   g_deg[NODES_MAX];
__device__ int   g_off[NODES_MAX + 1];
__device__ int   g_cur[NODES_MAX];
__device__ int   g_esrc[EDGES_MAX];
__device__ int   g_bsum[512];
__device__ int   g_bpre[512];
// split-bf16 weights, original [K,256] layout: 5 slots (K<=256)
__device__ __align__(16) __nv_bfloat16 g_wh[5 * 256 * 256];
__device__ __align__(16) __nv_bfloat16 g_wl[5 * 256 * 256];

// ---------------- degree / norm / CSR build ----------------
__global__ void init_deg_kernel(int* deg, int n) {
    int i = blockIdx.x * blockDim.x + threadIdx.x;
    if (i < n) deg[i] = 1;
}
__global__ void count_deg_kernel(const int* __restrict__ dst, int* deg, int E) {
    int i = blockIdx.x * blockDim.x + threadIdx.x;
    if (i < E) atomicAdd(&deg[dst[i]], 1);
}
__global__ void dinv_kernel(const int* __restrict__ deg, float* dinv, int n) {
    int i = blockIdx.x * blockDim.x + threadIdx.x;
    if (i < n) dinv[i] = rsqrtf((float)deg[i]);
}
// parallel scan, 3 stages
__global__ void bsum_kernel(const int* __restrict__ deg, int* bsum, int n) {
    __shared__ int sh[256];
    int i = blockIdx.x * 256 + threadIdx.x;
    sh[threadIdx.x] = (i < n) ? deg[i] - 1 : 0;
    __syncthreads();
    for (int o = 128; o > 0; o >>= 1) {
        if (threadIdx.x < o) sh[threadIdx.x] += sh[threadIdx.x + o];
        __syncthreads();
    }
    if (threadIdx.x == 0) bsum[blockIdx.x] = sh[0];
}
__global__ void bscan_kernel(const int* __restrict__ bsum, int* bpre, int nb, int* off, int n) {
    __shared__ int sh[512];
    int t = threadIdx.x;
    int v = (t < nb) ? bsum[t] : 0;
    sh[t] = v; __syncthreads();
    for (int o = 1; o < 512; o <<= 1) {
        int u = (t >= o) ? sh[t - o] : 0;
        __syncthreads();
        sh[t] += u;
        __syncthreads();
    }
    if (t < nb) bpre[t] = sh[t] - v;           // exclusive
    if (t == 511) off[n] = sh[511];            // total edge count
}
__global__ void off_kernel(const int* __restrict__ deg, const int* __restrict__ bpre,
                           int* __restrict__ off, int n) {
    __shared__ int sh[256];
    int i = blockIdx.x * 256 + threadIdx.x;
    int v = (i < n) ? deg[i] - 1 : 0;
    sh[threadIdx.x] = v; __syncthreads();
    for (int o = 1; o < 256; o <<= 1) {
        int u = (threadIdx.x >= o) ? sh[threadIdx.x - o] : 0;
        __syncthreads();
        sh[threadIdx.x] += u;
        __syncthreads();
    }
    if (i < n) off[i] = bpre[blockIdx.x] + sh[threadIdx.x] - v;
}
__global__ void cursor_copy_kernel(const int* __restrict__ off, int* cur, int n) {
    int i = blockIdx.x * blockDim.x + threadIdx.x;
    if (i < n) cur[i] = off[i];
}
__global__ void fill_kernel(const int* __restrict__ src, const int* __restrict__ dst,
                            int* cur, int* __restrict__ esrc, int E) {
    int i = blockIdx.x * blockDim.x + threadIdx.x;
    if (i < E) {
        int d = dst[i];
        int p = atomicAdd(&cur[d], 1);
        esrc[p] = src[i];
    }
}

// ---------------- weight prep: W[K,256] fp32 -> hi/lo bf16, same layout ----------------
__global__ void wprep_kernel(const float* __restrict__ W, __nv_bfloat16* __restrict__ Wh,
                             __nv_bfloat16* __restrict__ Wl, int total) {
    int idx = blockIdx.x * 256 + threadIdx.x;
    if (idx >= total) return;
    float f = W[idx];
    __nv_bfloat16 hb = __float2bfloat16_rn(f);
    Wh[idx] = hb;
    Wl[idx] = __float2bfloat16_rn(f - __bfloat162float(hb));
}

// ---------------- wmma split-bf16 GEMM (unchanged from R9) ----------------
#define PADA 40
#define PADB 136
#define OFF_AL 10240
#define OFF_BH 20480
#define OFF_BL 29184
#define WSMEM 65536

__global__ __launch_bounds__(256)
void wgemm_kernel(const float* __restrict__ A, const __nv_bfloat16* __restrict__ Bh,
                  const __nv_bfloat16* __restrict__ Bl, const float* __restrict__ bias,
                  float* __restrict__ C, int M, int K, int relu)
{
    extern __shared__ char smem[];
    __nv_bfloat16* sAh = (__nv_bfloat16*)(smem);
    __nv_bfloat16* sAl = (__nv_bfloat16*)(smem + OFF_AL);
    __nv_bfloat16* sBh = (__nv_bfloat16*)(smem + OFF_BH);
    __nv_bfloat16* sBl = (__nv_bfloat16*)(smem + OFF_BL);
    float* stage = (float*)smem;

    int tid = threadIdx.x;
    int wid = tid >> 5;
    int wm = wid >> 2;
    int wn = wid & 3;
    int row0 = blockIdx.x * 128;
    int col0 = blockIdx.y * 128;

    wmma::fragment<wmma::accumulator, 16, 16, 16, float> acc[4][2];
    #pragma unroll
    for (int i = 0; i < 4; i++)
        #pragma unroll
        for (int j = 0; j < 2; j++) wmma::fill_fragment(acc[i][j], 0.0f);

    for (int k0 = 0; k0 < K; k0 += 32) {
        #pragma unroll
        for (int it = 0; it < 4; it++) {
            int idx = it * 256 + tid;
            int r = idx >> 3;
            int c4 = (idx & 7) * 4;
            int grow = row0 + r;
            float4 f = (grow < M) ? *(const float4*)(A + (size_t)grow * K + k0 + c4)
                                  : make_float4(0.f, 0.f, 0.f, 0.f);
            uint32_t h01, h23, l01, l23;
            asm("cvt.rn.bf16x2.f32 %0, %1, %2;" : "=r"(h01) : "f"(f.y), "f"(f.x));
            asm("cvt.rn.bf16x2.f32 %0, %1, %2;" : "=r"(h23) : "f"(f.w), "f"(f.z));
            float r0 = f.x - __uint_as_float(h01 << 16);
            float r1 = f.y - __uint_as_float(h01 & 0xFFFF0000u);
            float r2 = f.z - __uint_as_float(h23 << 16);
            float r3 = f.w - __uint_as_float(h23 & 0xFFFF0000u);
            asm("cvt.rn.bf16x2.f32 %0, %1, %2;" : "=r"(l01) : "f"(r1), "f"(r0));
            asm("cvt.rn.bf16x2.f32 %0, %1, %2;" : "=r"(l23) : "f"(r3), "f"(r2));
            *(uint2*)(sAh + r * PADA + c4) = make_uint2(h01, h23);
            *(uint2*)(sAl + r * PADA + c4) = make_uint2(l01, l23);
        }
        #pragma unroll
        for (int it = 0; it < 2; it++) {
            int idx = it * 256 + tid;
            int r = idx >> 4;
            int c8 = (idx & 15) * 8;
            size_t go = (size_t)(k0 + r) * 256 + col0 + c8;
            *(uint4*)(sBh + r * PADB + c8) = *(const uint4*)(Bh + go);
            *(uint4*)(sBl + r * PADB + c8) = *(const uint4*)(Bl + go);
        }
        __syncthreads();

        #pragma unroll
        for (int ks = 0; ks < 2; ks++) {
            wmma::fragment<wmma::matrix_a, 16, 16, 16, __nv_bfloat16, wmma::row_major> ah[4], al[4];
            wmma::fragment<wmma::matrix_b, 16, 16, 16, __nv_bfloat16, wmma::row_major> bh[2], bl[2];
            #pragma unroll
            for (int i = 0; i < 4; i++) {
                wmma::load_matrix_sync(ah[i], sAh + (wm * 64 + i * 16) * PADA + ks * 16, PADA);
                wmma::load_matrix_sync(al[i], sAl + (wm * 64 + i * 16) * PADA + ks * 16, PADA);
            }
            #pragma unroll
            for (int j = 0; j < 2; j++) {
                wmma::load_matrix_sync(bh[j], sBh + (ks * 16) * PADB + wn * 32 + j * 16, PADB);
                wmma::load_matrix_sync(bl[j], sBl + (ks * 16) * PADB + wn * 32 + j * 16, PADB);
            }
            #pragma unroll
            for (int i = 0; i < 4; i++)
                #pragma unroll
                for (int j = 0; j < 2; j++) {
                    wmma::mma_sync(acc[i][j], ah[i], bh[j], acc[i][j]);
                    wmma::mma_sync(acc[i][j], ah[i], bl[j], acc[i][j]);
                    wmma::mma_sync(acc[i][j], al[i], bh[j], acc[i][j]);
                }
        }
        __syncthreads();
    }

    #pragma unroll
    for (int i = 0; i < 4; i++)
        #pragma unroll
        for (int j = 0; j < 2; j++)
            wmma::store_matrix_sync(stage + (wm * 64 + i * 16) * 128 + wn * 32 + j * 16,
                                    acc[i][j], 128, wmma::mem_row_major);
    __syncthreads();

    #pragma unroll
    for (int it = 0; it < 16; it++) {
        int idx = it * 256 + tid;
        int r = idx >> 5;
        int c4 = (idx & 31) * 4;
        int grow = row0 + r;
        if (grow < M) {
            float4 v = *(float4*)(stage + r * 128 + c4);
            if (bias) {
                v.x += bias[col0 + c4 + 0]; v.y += bias[col0 + c4 + 1];
                v.z += bias[col0 + c4 + 2]; v.w += bias[col0 + c4 + 3];
            }
            if (relu) {
                v.x = fmaxf(v.x, 0.f); v.y = fmaxf(v.y, 0.f);
                v.z = fmaxf(v.z, 0.f); v.w = fmaxf(v.w, 0.f);
            }
            *(float4*)(C + (size_t)grow * 256 + col0 + c4) = v;
        }
    }
}

// ---------------- fused aggregate, MLP-batched ----------------
// Warp per node. Lane-parallel edge metadata prefetch (esrc+dinv once, shfl broadcast),
// then 4-edge batches: all 8 row float4 loads issued before any FMA.
__global__ __launch_bounds__(256)
void aggregate_kernel(const float* __restrict__ m, const int* __restrict__ off,
                      const int* __restrict__ esrc, const float* __restrict__ dinv,
                      const float* __restrict__ bias, float* __restrict__ out, int n)
{
    int node = (blockIdx.x * blockDim.x + threadIdx.x) >> 5;
    int lane = threadIdx.x & 31;
    if (node >= n) return;

    float di = __ldg(&dinv[node]);
    const float4* bias4 = (const float4*)bias;
    const float4* mrow = (const float4*)(m + (size_t)node * HDIM);

    float4 a0 = bias4[lane];
    float4 a1 = bias4[lane + 32];

    // self-loop
    float ws = di * di;
    float4 v0 = mrow[lane];
    float4 v1 = mrow[lane + 32];
    a0.x = fmaf(ws, v0.x, a0.x); a0.y = fmaf(ws, v0.y, a0.y);
    a0.z = fmaf(ws, v0.z, a0.z); a0.w = fmaf(ws, v0.w, a0.w);
    a1.x = fmaf(ws, v1.x, a1.x); a1.y = fmaf(ws, v1.y, a1.y);
    a1.z = fmaf(ws, v1.z, a1.z); a1.w = fmaf(ws, v1.w, a1.w);

    int e0 = __ldg(&off[node]);
    int e1 = __ldg(&off[node + 1]);

    for (int base = e0; base < e1; base += 32) {
        // lane-parallel metadata fetch for up to 32 edges
        int eloc = base + lane;
        int sL = 0; float wL = 0.f;
        if (eloc < e1) {
            sL = __ldg(&esrc[eloc]);
            wL = __ldg(&dinv[sL]);
        }
        int cnt = e1 - base; if (cnt > 32) cnt = 32;

        for (int t0 = 0; t0 < cnt; t0 += 4) {
            int bc = cnt - t0; if (bc > 4) bc = 4;
            int ss[4]; float wv[4];
            #pragma unroll
            for (int t = 0; t < 4; t++) {
                ss[t] = __shfl_sync(0xFFFFFFFFu, sL, t0 + t);
                wv[t] = __shfl_sync(0xFFFFFFFFu, wL, t0 + t) * di;
            }
            float4 ua[4], ub[4];
            #pragma unroll
            for (int t = 0; t < 4; t++) {
                if (t < bc) {
                    const float4* sr = (const float4*)(m + (size_t)ss[t] * HDIM);
                    ua[t] = sr[lane];
                    ub[t] = sr[lane + 32];
                }
            }
            #pragma unroll
            for (int t = 0; t < 4; t++) {
                if (t < bc) {
                    float w = wv[t];
                    a0.x = fmaf(w, ua[t].x, a0.x); a0.y = fmaf(w, ua[t].y, a0.y);
                    a0.z = fmaf(w, ua[t].z, a0.z); a0.w = fmaf(w, ua[t].w, a0.w);
                    a1.x = fmaf(w, ub[t].x, a1.x); a1.y = fmaf(w, ub[t].y, a1.y);
                    a1.z = fmaf(w, ub[t].z, a1.z); a1.w = fmaf(w, ub[t].w, a1.w);
                }
            }
        }
    }

    a0.x = fmaxf(a0.x, 0.f); a0.y = fmaxf(a0.y, 0.f);
    a0.z = fmaxf(a0.z, 0.f); a0.w = fmaxf(a0.w, 0.f);
    a1.x = fmaxf(a1.x, 0.f); a1.y = fmaxf(a1.y, 0.f);
    a1.z = fmaxf(a1.z, 0.f); a1.w = fmaxf(a1.w, 0.f);

    float4* orow = (float4*)(out + (size_t)node * HDIM);
    orow[lane] = a0;
    orow[lane + 32] = a1;
}

extern "C" void kernel_launch(void* const* d_in, const int* in_sizes, int n_in,
                              void* d_out, int out_size)
{
    const float* x  = (const float*)d_in[0];
    const int*   ei = (const int*)d_in[1];
    const float* w1 = (const float*)d_in[2];
    const float* b1 = (const float*)d_in[3];
    const float* w2 = (const float*)d_in[4];
    const float* b2 = (const float*)d_in[5];
    const float* gw = (const float*)d_in[6];
    const float* gb = (const float*)d_in[7];

    int N = in_sizes[0] / FIN;
    int E = in_sizes[1] / 2;
    int L = in_sizes[6] / (HDIM * HDIM);
    const int* srcp = ei;
    const int* dstp = ei + E;

    float *h, *m, *dinv;
    int *deg, *off, *cur, *esrc, *bsum, *bpre;
    __nv_bfloat16 *wh, *wl;
    cudaGetSymbolAddress((void**)&h,    g_h);
    cudaGetSymbolAddress((void**)&m,    g_m);
    cudaGetSymbolAddress((void**)&dinv, g_dinv);
    cudaGetSymbolAddress((void**)&deg,  g_deg);
    cudaGetSymbolAddress((void**)&off,  g_off);
    cudaGetSymbolAddress((void**)&cur,  g_cur);
    cudaGetSymbolAddress((void**)&esrc, g_esrc);
    cudaGetSymbolAddress((void**)&bsum, g_bsum);
    cudaGetSymbolAddress((void**)&bpre, g_bpre);
    cudaGetSymbolAddress((void**)&wh,   g_wh);
    cudaGetSymbolAddress((void**)&wl,   g_wl);

    cudaFuncSetAttribute(wgemm_kernel, cudaFuncAttributeMaxDynamicSharedMemorySize, WSMEM);

    int nb = (N + 255) / 256;
    int eb = (E + 255) / 256;

    init_deg_kernel<<<nb, 256>>>(deg, N);
    count_deg_kernel<<<eb, 256>>>(dstp, deg, E);
    dinv_kernel<<<nb, 256>>>(deg, dinv, N);
    bsum_kernel<<<nb, 256>>>(deg, bsum, N);
    bscan_kernel<<<1, 512>>>(bsum, bpre, nb, off, N);
    off_kernel<<<nb, 256>>>(deg, bpre, off, N);
    cursor_copy_kernel<<<nb, 256>>>(off, cur, N);
    fill_kernel<<<eb, 256>>>(srcp, dstp, cur, esrc, E);

    const size_t WS = 256 * 256;
    wprep_kernel<<<(FIN * 256 + 255) / 256, 256>>>(w1, wh, wl, FIN * 256);
    wprep_kernel<<<(HDIM * 256 + 255) / 256, 256>>>(w2, wh + WS, wl + WS, HDIM * 256);
    for (int l = 0; l < L; l++)
        wprep_kernel<<<(HDIM * 256 + 255) / 256, 256>>>(gw + (size_t)l * HDIM * HDIM,
                                                        wh + WS * (2 + l), wl + WS * (2 + l),
                                                        HDIM * 256);

    dim3 gemm_grid((N + 127) / 128, 2);

    wgemm_kernel<<<gemm_grid, 256, WSMEM>>>(x, wh, wl, b1, m, N, FIN, 1);
    wgemm_kernel<<<gemm_grid, 256, WSMEM>>>(m, wh + WS, wl + WS, b2, h, N, HDIM, 0);

    int agg_blocks = (int)(((long long)N * 32 + 255) / 256);

    for (int l = 0; l < L; l++) {
        wgemm_kernel<<<gemm_grid, 256, WSMEM>>>(h, wh + WS * (2 + l), wl + WS * (2 + l),
                                                nullptr, m, N, HDIM, 0);
        float* dest = (l == L - 1) ? (float*)d_out : h;
        aggregate_kernel<<<agg_blocks, 256>>>(m, off, esrc, dinv, gb + (size_t)l * HDIM, dest, N);
    }
}

// round 11
// speedup vs baseline: 1.2486x; 1.2486x over previous
#include <cuda_runtime.h>
#include <cuda_bf16.h>
#include <mma.h>
#include <cstdint>

using namespace nvcuda;

#define NODES_MAX 100000
#define EDGES_MAX 300000
#define HDIM 256
#define FIN 128

// ---------------- scratch (allocation-free rule: __device__ globals) ----------------
__device__ __align__(16) float g_h[(size_t)NODES_MAX * HDIM];
__device__ __align__(16) float g_m[(size_t)NODES_MAX * HDIM];
__device__ float g_dinv[NODES_MAX];
__device__ int   g_deg[NODES_MAX];
__device__ int   g_off[NODES_MAX + 1];
__device__ int   g_cur[NODES_MAX];
__device__ int   g_esrc[EDGES_MAX];
__device__ int   g_bsum[512];
__device__ int   g_bpre[512];
__device__ __align__(16) __nv_bfloat16 g_wh[5 * 256 * 256];
__device__ __align__(16) __nv_bfloat16 g_wl[5 * 256 * 256];

// ---------------- degree / norm / CSR build ----------------
__global__ void init_deg_kernel(int* deg, int n) {
    int i = blockIdx.x * blockDim.x + threadIdx.x;
    if (i < n) deg[i] = 1;
}
__global__ void count_deg_kernel(const int* __restrict__ dst, int* deg, int E) {
    int i = blockIdx.x * blockDim.x + threadIdx.x;
    if (i < E) atomicAdd(&deg[dst[i]], 1);
}
__global__ void dinv_kernel(const int* __restrict__ deg, float* dinv, int n) {
    int i = blockIdx.x * blockDim.x + threadIdx.x;
    if (i < n) dinv[i] = rsqrtf((float)deg[i]);
}
__global__ void bsum_kernel(const int* __restrict__ deg, int* bsum, int n) {
    __shared__ int sh[256];
    int i = blockIdx.x * 256 + threadIdx.x;
    sh[threadIdx.x] = (i < n) ? deg[i] - 1 : 0;
    __syncthreads();
    for (int o = 128; o > 0; o >>= 1) {
        if (threadIdx.x < o) sh[threadIdx.x] += sh[threadIdx.x + o];
        __syncthreads();
    }
    if (threadIdx.x == 0) bsum[blockIdx.x] = sh[0];
}
__global__ void bscan_kernel(const int* __restrict__ bsum, int* bpre, int nb, int* off, int n) {
    __shared__ int sh[512];
    int t = threadIdx.x;
    int v = (t < nb) ? bsum[t] : 0;
    sh[t] = v; __syncthreads();
    for (int o = 1; o < 512; o <<= 1) {
        int u = (t >= o) ? sh[t - o] : 0;
        __syncthreads();
        sh[t] += u;
        __syncthreads();
    }
    if (t < nb) bpre[t] = sh[t] - v;
    if (t == 511) off[n] = sh[511];
}
// writes both off and cur (cursor_copy folded in)
__global__ void off_kernel(const int* __restrict__ deg, const int* __restrict__ bpre,
                           int* __restrict__ off, int* __restrict__ cur, int n) {
    __shared__ int sh[256];
    int i = blockIdx.x * 256 + threadIdx.x;
    int v = (i < n) ? deg[i] - 1 : 0;
    sh[threadIdx.x] = v; __syncthreads();
    for (int o = 1; o < 256; o <<= 1) {
        int u = (threadIdx.x >= o) ? sh[threadIdx.x - o] : 0;
        __syncthreads();
        sh[threadIdx.x] += u;
        __syncthreads();
    }
    if (i < n) {
        int val = bpre[blockIdx.x] + sh[threadIdx.x] - v;
        off[i] = val;
        cur[i] = val;
    }
}
__global__ void fill_kernel(const int* __restrict__ src, const int* __restrict__ dst,
                            int* cur, int* __restrict__ esrc, int E) {
    int i = blockIdx.x * blockDim.x + threadIdx.x;
    if (i < E) {
        int d = dst[i];
        int p = atomicAdd(&cur[d], 1);
        esrc[p] = src[i];
    }
}

// ---------------- weight prep ----------------
__global__ void wprep_kernel(const float* __restrict__ W, __nv_bfloat16* __restrict__ Wh,
                             __nv_bfloat16* __restrict__ Wl, int total) {
    int idx = blockIdx.x * 256 + threadIdx.x;
    if (idx >= total) return;
    float f = W[idx];
    __nv_bfloat16 hb = __float2bfloat16_rn(f);
    Wh[idx] = hb;
    Wl[idx] = __float2bfloat16_rn(f - __bfloat162float(hb));
}

// ---------------- double-buffered wmma split-bf16 GEMM ----------------
#define PADA 40
#define PADB 136
#define SZ_A (128 * PADA * 2)         // 10240 B per A matrix per stage
#define SZ_B (32 * PADB * 2)          // 8704 B per B matrix per stage
#define STAGE_SZ (2 * SZ_A + 2 * SZ_B) // 37888
#define WSMEM (2 * STAGE_SZ)           // 75776 (epilogue fp32 stage 65536 fits)

__device__ __forceinline__ void cp16(void* sdst, const void* g) {
    uint32_t sa = (uint32_t)__cvta_generic_to_shared(sdst);
    asm volatile("cp.async.cg.shared.global [%0], [%1], 16;" :: "r"(sa), "l"(g));
}

__global__ __launch_bounds__(256)
void wgemm_kernel(const float* __restrict__ A, const __nv_bfloat16* __restrict__ Bh,
                  const __nv_bfloat16* __restrict__ Bl, const float* __restrict__ bias,
                  float* __restrict__ C, int M, int K, int relu)
{
    extern __shared__ char smem[];
    int tid = threadIdx.x;
    int wid = tid >> 5;
    int wm = wid >> 2;
    int wn = wid & 3;
    int row0 = blockIdx.x * 128;
    int col0 = blockIdx.y * 128;
    float* stage = (float*)smem;

    wmma::fragment<wmma::accumulator, 16, 16, 16, float> acc[4][2];
    #pragma unroll
    for (int i = 0; i < 4; i++)
        #pragma unroll
        for (int j = 0; j < 2; j++) wmma::fill_fragment(acc[i][j], 0.0f);

    int NC = K >> 5;
    float4 areg[4];

    // A-tile map: idx=it*256+tid -> r=idx>>3 (0..127), c4=(idx&7)*4 (0..28)
    #define PREFETCH_A(kc) do { \
        _Pragma("unroll") \
        for (int it = 0; it < 4; it++) { \
            int idx = it * 256 + tid; \
            int r = idx >> 3, c4 = (idx & 7) * 4; \
            int grow = row0 + r; \
            areg[it] = (grow < M) ? *(const float4*)(A + (size_t)grow * K + (kc) * 32 + c4) \
                                  : make_float4(0.f, 0.f, 0.f, 0.f); \
        } } while (0)

    #define ISSUE_B(kc, s) do { \
        char* base = smem + (s) * STAGE_SZ; \
        __nv_bfloat16* bh_ = (__nv_bfloat16*)(base + 2 * SZ_A); \
        __nv_bfloat16* bl_ = (__nv_bfloat16*)(base + 2 * SZ_A + SZ_B); \
        _Pragma("unroll") \
        for (int it = 0; it < 2; it++) { \
            int idx = it * 256 + tid; \
            int r = idx >> 4, c8 = (idx & 15) * 8; \
            size_t go = (size_t)((kc) * 32 + r) * 256 + col0 + c8; \
            cp16(bh_ + r * PADB + c8, Bh + go); \
            cp16(bl_ + r * PADB + c8, Bl + go); \
        } \
        asm volatile("cp.async.commit_group;"); } while (0)

    PREFETCH_A(0);
    ISSUE_B(0, 0);

    for (int kc = 0; kc < NC; kc++) {
        int s = kc & 1;
        char* base = smem + s * STAGE_SZ;
        __nv_bfloat16* sAh = (__nv_bfloat16*)(base);
        __nv_bfloat16* sAl = (__nv_bfloat16*)(base + SZ_A);
        __nv_bfloat16* sBh = (__nv_bfloat16*)(base + 2 * SZ_A);
        __nv_bfloat16* sBl = (__nv_bfloat16*)(base + 2 * SZ_A + SZ_B);

        // convert prefetched A regs -> split bf16 smem
        #pragma unroll
        for (int it = 0; it < 4; it++) {
            int idx = it * 256 + tid;
            int r = idx >> 3, c4 = (idx & 7) * 4;
            float4 f = areg[it];
            uint32_t h01, h23, l01, l23;
            asm("cvt.rn.bf16x2.f32 %0, %1, %2;" : "=r"(h01) : "f"(f.y), "f"(f.x));
            asm("cvt.rn.bf16x2.f32 %0, %1, %2;" : "=r"(h23) : "f"(f.w), "f"(f.z));
            float r0 = f.x - __uint_as_float(h01 << 16);
            float r1 = f.y - __uint_as_float(h01 & 0xFFFF0000u);
            float r2 = f.z - __uint_as_float(h23 << 16);
            float r3 = f.w - __uint_as_float(h23 & 0xFFFF0000u);
            asm("cvt.rn.bf16x2.f32 %0, %1, %2;" : "=r"(l01) : "f"(r1), "f"(r0));
            asm("cvt.rn.bf16x2.f32 %0, %1, %2;" : "=r"(l23) : "f"(r3), "f"(r2));
            *(uint2*)(sAh + r * PADA + c4) = make_uint2(h01, h23);
            *(uint2*)(sAl + r * PADA + c4) = make_uint2(l01, l23);
        }

        asm volatile("cp.async.wait_group 0;" ::: "memory");
        __syncthreads();

        if (kc + 1 < NC) {
            ISSUE_B(kc + 1, s ^ 1);
            PREFETCH_A(kc + 1);
        }

        #pragma unroll
        for (int ks = 0; ks < 2; ks++) {
            wmma::fragment<wmma::matrix_b, 16, 16, 16, __nv_bfloat16, wmma::row_major> bh[2], bl[2];
            #pragma unroll
            for (int j = 0; j < 2; j++) {
                wmma::load_matrix_sync(bh[j], sBh + (ks * 16) * PADB + wn * 32 + j * 16, PADB);
                wmma::load_matrix_sync(bl[j], sBl + (ks * 16) * PADB + wn * 32 + j * 16, PADB);
            }
            #pragma unroll
            for (int i = 0; i < 4; i++) {
                wmma::fragment<wmma::matrix_a, 16, 16, 16, __nv_bfloat16, wmma::row_major> ah, al;
                wmma::load_matrix_sync(ah, sAh + (wm * 64 + i * 16) * PADA + ks * 16, PADA);
                wmma::load_matrix_sync(al, sAl + (wm * 64 + i * 16) * PADA + ks * 16, PADA);
                #pragma unroll
                for (int j = 0; j < 2; j++) {
                    wmma::mma_sync(acc[i][j], ah, bh[j], acc[i][j]);
                    wmma::mma_sync(acc[i][j], ah, bl[j], acc[i][j]);
                    wmma::mma_sync(acc[i][j], al, bh[j], acc[i][j]);
                }
            }
        }
    }

    __syncthreads();   // before stage reuse

    #pragma unroll
    for (int i = 0; i < 4; i++)
        #pragma unroll
        for (int j = 0; j < 2; j++)
            wmma::store_matrix_sync(stage + (wm * 64 + i * 16) * 128 + wn * 32 + j * 16,
                                    acc[i][j], 128, wmma::mem_row_major);
    __syncthreads();

    #pragma unroll
    for (int it = 0; it < 16; it++) {
        int idx = it * 256 + tid;
        int r = idx >> 5;
        int c4 = (idx & 31) * 4;
        int grow = row0 + r;
        if (grow < M) {
            float4 v = *(float4*)(stage + r * 128 + c4);
            if (bias) {
                v.x += bias[col0 + c4 + 0]; v.y += bias[col0 + c4 + 1];
                v.z += bias[col0 + c4 + 2]; v.w += bias[col0 + c4 + 3];
            }
            if (relu) {
                v.x = fmaxf(v.x, 0.f); v.y = fmaxf(v.y, 0.f);
                v.z = fmaxf(v.z, 0.f); v.w = fmaxf(v.w, 0.f);
            }
            *(float4*)(C + (size_t)grow * 256 + col0 + c4) = v;
        }
    }
    #undef PREFETCH_A
    #undef ISSUE_B
}

// ---------------- fused aggregate: 2 warps per node (128 cols each) ----------------
__global__ __launch_bounds__(256)
void aggregate_kernel(const float* __restrict__ m, const int* __restrict__ off,
                      const int* __restrict__ esrc, const float* __restrict__ dinv,
                      const float* __restrict__ bias, float* __restrict__ out, int n)
{
    int gw = (blockIdx.x * blockDim.x + threadIdx.x) >> 5;
    int node = gw >> 1;
    int half = gw & 1;
    int lane = threadIdx.x & 31;
    if (node >= n) return;
    int j = half * 32 + lane;    // float4 column index 0..63

    float di = __ldg(&dinv[node]);
    float4 a = ((const float4*)bias)[j];

    float ws = di * di;
    float4 v = ((const float4*)(m + (size_t)node * HDIM))[j];
    a.x = fmaf(ws, v.x, a.x); a.y = fmaf(ws, v.y, a.y);
    a.z = fmaf(ws, v.z, a.z); a.w = fmaf(ws, v.w, a.w);

    int e = __ldg(&off[node]);
    int e1 = __ldg(&off[node + 1]);

    if (e < e1) {
        int s = __ldg(&esrc[e]);
        float wd = __ldg(&dinv[s]);
        while (true) {
            float4 u = ((const float4*)(m + (size_t)s * HDIM))[j];
            int sn = 0; float wdn = 0.f;
            if (e + 1 < e1) { sn = __ldg(&esrc[e + 1]); wdn = __ldg(&dinv[sn]); }
            float w = wd * di;
            a.x = fmaf(w, u.x, a.x); a.y = fmaf(w, u.y, a.y);
            a.z = fmaf(w, u.z, a.z); a.w = fmaf(w, u.w, a.w);
            e++;
            if (e >= e1) break;
            s = sn; wd = wdn;
        }
    }

    a.x = fmaxf(a.x, 0.f); a.y = fmaxf(a.y, 0.f);
    a.z = fmaxf(a.z, 0.f); a.w = fmaxf(a.w, 0.f);
    ((float4*)(out + (size_t)node * HDIM))[j] = a;
}

extern "C" void kernel_launch(void* const* d_in, const int* in_sizes, int n_in,
                              void* d_out, int out_size)
{
    const float* x  = (const float*)d_in[0];
    const int*   ei = (const int*)d_in[1];
    const float* w1 = (const float*)d_in[2];
    const float* b1 = (const float*)d_in[3];
    const float* w2 = (const float*)d_in[4];
    const float* b2 = (const float*)d_in[5];
    const float* gw = (const float*)d_in[6];
    const float* gb = (const float*)d_in[7];

    int N = in_sizes[0] / FIN;
    int E = in_sizes[1] / 2;
    int L = in_sizes[6] / (HDIM * HDIM);
    const int* srcp = ei;
    const int* dstp = ei + E;

    float *h, *m, *dinv;
    int *deg, *off, *cur, *esrc, *bsum, *bpre;
    __nv_bfloat16 *wh, *wl;
    cudaGetSymbolAddress((void**)&h,    g_h);
    cudaGetSymbolAddress((void**)&m,    g_m);
    cudaGetSymbolAddress((void**)&dinv, g_dinv);
    cudaGetSymbolAddress((void**)&deg,  g_deg);
    cudaGetSymbolAddress((void**)&off,  g_off);
    cudaGetSymbolAddress((void**)&cur,  g_cur);
    cudaGetSymbolAddress((void**)&esrc, g_esrc);
    cudaGetSymbolAddress((void**)&bsum, g_bsum);
    cudaGetSymbolAddress((void**)&bpre, g_bpre);
    cudaGetSymbolAddress((void**)&wh,   g_wh);
    cudaGetSymbolAddress((void**)&wl,   g_wl);

    cudaFuncSetAttribute(wgemm_kernel, cudaFuncAttributeMaxDynamicSharedMemorySize, WSMEM);

    int nb = (N + 255) / 256;
    int eb = (E + 255) / 256;

    init_deg_kernel<<<nb, 256>>>(deg, N);
    count_deg_kernel<<<eb, 256>>>(dstp, deg, E);
    dinv_kernel<<<nb, 256>>>(deg, dinv, N);
    bsum_kernel<<<nb, 256>>>(deg, bsum, N);
    bscan_kernel<<<1, 512>>>(bsum, bpre, nb, off, N);
    off_kernel<<<nb, 256>>>(deg, bpre, off, cur, N);
    fill_kernel<<<eb, 256>>>(srcp, dstp, cur, esrc, E);

    const size_t WS = 256 * 256;
    wprep_kernel<<<(FIN * 256 + 255) / 256, 256>>>(w1, wh, wl, FIN * 256);
    wprep_kernel<<<(HDIM * 256 + 255) / 256, 256>>>(w2, wh + WS, wl + WS, HDIM * 256);
    wprep_kernel<<<(L * HDIM * 256 + 255) / 256, 256>>>(gw, wh + 2 * WS, wl + 2 * WS,
                                                        L * HDIM * 256);

    dim3 gemm_grid((N + 127) / 128, 2);

    wgemm_kernel<<<gemm_grid, 256, WSMEM>>>(x, wh, wl, b1, m, N, FIN, 1);
    wgemm_kernel<<<gemm_grid, 256, WSMEM>>>(m, wh + WS, wl + WS, b2, h, N, HDIM, 0);

    int agg_blocks = (int)(((long long)N * 64 + 255) / 256);

    for (int l = 0; l < L; l++) {
        wgemm_kernel<<<gemm_grid, 256, WSMEM>>>(h, wh + WS * (2 + l), wl + WS * (2 + l),
                                                nullptr, m, N, HDIM, 0);
        float* dest = (l == L - 1) ? (float*)d_out : h;
        aggregate_kernel<<<agg_blocks, 256>>>(m, off, esrc, dinv, gb + (size_t)l * HDIM, dest, N);
    }
}